// round 9
// baseline (speedup 1.0000x reference)
#include <cuda_runtime.h>
#include <math.h>

// Problem constants: B=1048576, M=8, K=3, R=8
#define M 8
#define Kc 3
#define R 8
#define NPAIR 4          // rule pairs (f32x2 lanes = 2 rules)
#define PW 56            // floats per packed pair row (26 entries*2, padded; 16B aligned)
#define TPB 128          // threads per block
#define RPT 4            // row passes per warp (16 rows per pass)
#define ROWS_PER_BLOCK (TPB / 2 * RPT)   // 4 warps * 16 rows * 4 passes = 256

typedef unsigned long long u64;

static __device__ __forceinline__ u64 pk2(float lo, float hi) {
    u64 r; asm("mov.b64 %0, {%1,%2};" : "=l"(r) : "f"(lo), "f"(hi)); return r;
}
static __device__ __forceinline__ void upk2(u64 v, float& lo, float& hi) {
    asm("mov.b64 {%0,%1}, %2;" : "=f"(lo), "=f"(hi) : "l"(v));
}
static __device__ __forceinline__ u64 fma2(u64 a, u64 b, u64 c) {
    u64 d; asm("fma.rn.f32x2 %0, %1, %2, %3;" : "=l"(d) : "l"(a), "l"(b), "l"(c)); return d;
}
static __device__ __forceinline__ float ex2f(float v) {
    float r; asm("ex2.approx.f32 %0, %1;" : "=f"(r) : "f"(v)); return r;
}
static __device__ __forceinline__ float rcpf(float v) {
    float r; asm("rcp.approx.f32 %0, %1;" : "=f"(r) : "f"(v)); return r;
}

__global__ __launch_bounds__(TPB, 5)
void anfis_kernel(const float* __restrict__ x,
                  const float* __restrict__ c,
                  const float* __restrict__ log_sigma,
                  const float* __restrict__ cons,      // (R, M+1)
                  const int*   __restrict__ rules,     // (R, M)
                  float* __restrict__ out, int B)
{
    // Packed entry j (float2 over rule pair p = rules 2p,2p+1):
    //  j=0..7 : a_m = -h*log2(e) ; j=8..15: b_m = 2*h*c*log2(e)
    //  j=16   : k0 = -(sum h*c^2)*log2(e) ; j=17: bias ; j=18..25: w_m
    __shared__ float s_raw[R][26];
    __shared__ __align__(16) float s_pack[NPAIR * PW];

    const int tid = threadIdx.x;
    const float L2E = 1.4426950408889634f;

    if (tid < R) {
        const int r = tid;
        float k0 = 0.f;
        #pragma unroll
        for (int m = 0; m < M; m++) {
            int k = rules[r * M + m];
            float sg = expf(log_sigma[m * Kc + k]) + 1e-6f;
            float h  = 0.5f / (sg * sg);
            float cc = c[m * Kc + k];
            s_raw[r][m]      = -h * L2E;
            s_raw[r][8 + m]  = 2.f * h * cc * L2E;
            k0 -= h * cc * cc;
            s_raw[r][18 + m] = cons[r * (M + 1) + 1 + m];
        }
        s_raw[r][16] = k0 * L2E;
        s_raw[r][17] = cons[r * (M + 1)];
    }
    __syncthreads();
    if (tid < NPAIR * 28) {
        const int p = tid / 28, j = tid % 28;
        float v0 = (j < 26) ? s_raw[2 * p][j]     : 0.f;
        float v1 = (j < 26) ? s_raw[2 * p + 1][j] : 0.f;
        s_pack[p * PW + 2 * j]     = v0;
        s_pack[p * PW + 2 * j + 1] = v1;
    }
    __syncthreads();

    const int warp = tid >> 5;
    const int lane = tid & 31;
    const int half = lane >> 4;          // 0: rules 0-3 (pairs 0,1); 1: rules 4-7 (pairs 2,3)
    const int lrow = lane & 15;          // row slot within pass

    // first row handled by this thread (lanes l and l+16 share a row)
    const int base = blockIdx.x * ROWS_PER_BLOCK + warp * (16 * RPT) + lrow;
    if (base >= B) return;   // B=1048576 divisible by 256: all threads fully active

    // ---- load x rows (both halves load the same row; L1 broadcast) ----
    float xv[RPT][M];
    #pragma unroll
    for (int i = 0; i < RPT; i++) {
        const int b = base + i * 16;
        const float4 xa = *(const float4*)(x + (size_t)b * M);
        const float4 xb = *(const float4*)(x + (size_t)b * M + 4);
        xv[i][0]=xa.x; xv[i][1]=xa.y; xv[i][2]=xa.z; xv[i][3]=xa.w;
        xv[i][4]=xb.x; xv[i][5]=xb.y; xv[i][6]=xb.z; xv[i][7]=xb.w;
    }

    float f[RPT][4], yr[RPT][4];   // this half's 4 rules

    #pragma unroll
    for (int p = 0; p < 2; p++) {
        const int pp = half * 2 + p;                    // this half's pair index
        const u64* S = (const u64*)(s_pack + pp * PW);  // 26 packed entries

        u64 e[RPT], t[RPT];
        #pragma unroll
        for (int i = 0; i < RPT; i++) { e[i] = S[16]; t[i] = S[17]; }

        #pragma unroll
        for (int m = 0; m < M; m++) {
            const u64 A = S[m], Bc = S[8 + m], W = S[18 + m];
            #pragma unroll
            for (int i = 0; i < RPT; i++) {
                const u64 px = pk2(xv[i][m], xv[i][m]);   // rematerializable mov
                e[i] = fma2(fma2(A, px, Bc), px, e[i]);
                t[i] = fma2(W, px, t[i]);
            }
        }

        #pragma unroll
        for (int i = 0; i < RPT; i++) {
            float ea, eb;
            upk2(e[i], ea, eb);
            f[i][2*p]   = ex2f(ea);
            f[i][2*p+1] = ex2f(eb);
            upk2(t[i], yr[i][2*p], yr[i][2*p+1]);
        }
    }

    // ---- per-row: cross-half fsum, normalize, store everything ----
    #pragma unroll
    for (int i = 0; i < RPT; i++) {
        const int b = base + i * 16;

        // store y_r (no normalization needed): half-warp float4 tiles 512B/warp
        float4* yo = (float4*)(out + (size_t)B * 9 + (size_t)b * R + half * 4);
        *yo = make_float4(yr[i][0], yr[i][1], yr[i][2], yr[i][3]);

        float fs = (f[i][0] + f[i][1]) + (f[i][2] + f[i][3]);
        fs += __shfl_xor_sync(0xffffffffu, fs, 16);      // add other half's 4 rules

        const float inv = rcpf(fs + 1e-8f);

        float wn0 = f[i][0] * inv, wn1 = f[i][1] * inv;
        float wn2 = f[i][2] * inv, wn3 = f[i][3] * inv;

        float4* wo = (float4*)(out + (size_t)B + (size_t)b * R + half * 4);
        *wo = make_float4(wn0, wn1, wn2, wn3);

        // y = sum over all 8 rules of wn*yr (partial per half, then exchange)
        float yp = fmaf(wn0, yr[i][0], fmaf(wn1, yr[i][1],
                   fmaf(wn2, yr[i][2], wn3 * yr[i][3])));
        yp += __shfl_xor_sync(0xffffffffu, yp, 16);
        if (half == 0) out[b] = yp;
    }
}

extern "C" void kernel_launch(void* const* d_in, const int* in_sizes, int n_in,
                              void* d_out, int out_size)
{
    const float* x         = (const float*)d_in[0];
    const float* c         = (const float*)d_in[1];
    const float* log_sigma = (const float*)d_in[2];
    const float* cons      = (const float*)d_in[3];
    const int*   rules     = (const int*)d_in[4];
    float* out = (float*)d_out;

    const int B = in_sizes[0] / M;   // 1048576
    const int blocks = (B + ROWS_PER_BLOCK - 1) / ROWS_PER_BLOCK;  // 4096
    anfis_kernel<<<blocks, TPB>>>(x, c, log_sigma, cons, rules, out, B);
}